// round 10
// baseline (speedup 1.0000x reference)
#include <cuda_runtime.h>
#include <cuda_fp16.h>
#include <cstdint>
#include <math.h>

#define HIDDEN   256
#define NCLS     104
#define DIN      106
#define GX       128
#define NT       13          // n-tiles of 8
#define NSLICE   16          // k-slices of 16 (K=256)
#define ROWS_B   128         // rows per block
#define MAXG     4096
#define WFRAG    (NT * 3 * 32)   // 1248 uint2 fragments per k-slice (hi only)

// ---------------- device scratch (no cudaMalloc allowed) ----------------
__device__ float g_readout[MAXG * NCLS];
// Pre-packed fp16 weight B-fragments (hi only): [slice][ntile][stream][lane] -> {b0,b1}
// stream 0 = Wg rows [0,256), 1 = Wg rows [256,512), 2 = Wt
__device__ uint2 WB_pre[NSLICE * WFRAG];

// ---------------- helpers ----------------
__device__ __forceinline__ unsigned packh(float a, float b) {
    __half2 t = __floats2half2_rn(a, b);
    return *reinterpret_cast<unsigned*>(&t);
}
__device__ __forceinline__ void splith(float v, float& hi, float& lo) {
    __half h = __float2half_rn(v);
    hi = __half2float(h);
    lo = v - hi;
}
__device__ __forceinline__ void mma16816(float c[4], const unsigned a[4],
                                         unsigned b0, unsigned b1) {
    asm volatile(
        "mma.sync.aligned.m16n8k16.row.col.f32.f16.f16.f32 "
        "{%0,%1,%2,%3}, {%4,%5,%6,%7}, {%8,%9}, {%0,%1,%2,%3};"
        : "+f"(c[0]), "+f"(c[1]), "+f"(c[2]), "+f"(c[3])
        : "r"(a[0]), "r"(a[1]), "r"(a[2]), "r"(a[3]), "r"(b0), "r"(b1));
}

// ---------------- prep kernels ----------------
__global__ void zero_readout_k(float* __restrict__ p, int n) {
    int i = blockIdx.x * blockDim.x + threadIdx.x;
    if (i < n) p[i] = 0.0f;
}

__global__ void prep_weights(const float* __restrict__ Wg,
                             const float* __restrict__ Wt) {
    int idx = blockIdx.x * blockDim.x + threadIdx.x;
    if (idx >= NSLICE * WFRAG) return;
    int lane = idx & 31;
    int rest = idx >> 5;
    int stream = rest % 3; rest /= 3;
    int j = rest % NT;
    int s = rest / NT;
    int n = j * 8 + (lane >> 2);
    int kk = (lane & 3) * 2;
    int k0 = s * 16;

    float v[4];
    const int koffs[4] = {kk, kk + 1, kk + 8, kk + 9};
#pragma unroll
    for (int q = 0; q < 4; q++) {
        int k = k0 + koffs[q];
        float val;
        if (stream == 0)      val = Wg[k * NCLS + n];
        else if (stream == 1) val = Wg[(256 + k) * NCLS + n];
        else                  val = Wt[k * NCLS + n];
        v[q] = val;
    }
    WB_pre[idx] = make_uint2(packh(v[0], v[1]), packh(v[2], v[3]));
}

// ---------------- main fused kernel ----------------
// smem layout (dynamic, 53760 B):
//   [0      , 24576)  A planes: unsigned[2 buf][3 plane][8 tile][32 lane][4]
//                     plane 0 = init_hi, 1 = fin_hi, 2 = fin_lo   (16B lane stride, conflict-free)
//   [24576  , 44544)  Wsm: uint2[2 buf][1248]
//   [0      , 53248)  Snw: float[128][104]   (epilogue reuse)
//   [53248  , 53760)  gid_s: int[128]
extern "C" __global__ void __launch_bounds__(256, 1)
readout_mma(const float* __restrict__ init_ns,
            const float* __restrict__ fin_ns,
            const int*   __restrict__ gids,
            const float* __restrict__ bg,
            const float* __restrict__ bt,
            float*       __restrict__ readout,
            int N)
{
    extern __shared__ char smraw[];
    unsigned* Apl   = (unsigned*)smraw;                 // plane base, unsigned units
    uint2*    Wsm   = (uint2*)(smraw + 24576);
    float*    Snw   = (float*)smraw;
    int*      gid_s = (int*)(smraw + 53248);

    const int tid = threadIdx.x;
    const int n0  = blockIdx.x * ROWS_B;
    const int nvalid = min(ROWS_B, N - n0);

    if (tid < ROWS_B) gid_s[tid] = (tid < nvalid) ? gids[n0 + tid] : -1;

    // ---- compute-side identities ----
    const int w     = tid >> 5;
    const int lane  = tid & 31;
    const int wset  = w >> 2;            // 0: ntiles 0-6, 1: ntiles 7-12
    const int rgrp  = w & 3;             // which 32-row group
    const int jstart = wset * 7;
    const int jcount = wset ? 6 : 7;
    const int gid   = lane >> 2;
    const int tig   = lane & 3;

    float accg[2][7][4];
    float acct[2][7][4];
#pragma unroll
    for (int mt = 0; mt < 2; mt++)
#pragma unroll
        for (int jj = 0; jj < 7; jj++)
#pragma unroll
            for (int q = 0; q < 4; q++) { accg[mt][jj][q] = 0.f; acct[mt][jj][q] = 0.f; }

    // ---- staging identities: thread -> (mat, tilepair, lane) ----
    const int s_mat  = tid >> 7;          // 0 init, 1 fin
    const int s_tp   = (tid >> 5) & 3;    // tile pair
    const int s_lane = tid & 31;
    const int s_gid  = s_lane >> 2;
    const int s_tig  = s_lane & 3;
    const float* s_base = s_mat ? fin_ns : init_ns;

    // two register prefetch sets, keyed by slice parity
    float2 fv[2][2][4];
    uint2  wreg[2][5];

    const float2 z2 = make_float2(0.f, 0.f);

    auto ldga = [&](int s, int p) {
#pragma unroll
        for (int ti = 0; ti < 2; ti++) {
            int tile = s_tp * 2 + ti;
            int r0 = tile * 16 + s_gid;
            int r1 = r0 + 8;
            const float* p0 = s_base + (size_t)(n0 + r0) * HIDDEN + s * 16 + s_tig * 2;
            const float* p1 = s_base + (size_t)(n0 + r1) * HIDDEN + s * 16 + s_tig * 2;
            bool v0 = r0 < nvalid, v1 = r1 < nvalid;
            fv[p][ti][0] = v0 ? *(const float2*)p0       : z2;
            fv[p][ti][1] = v1 ? *(const float2*)p1       : z2;
            fv[p][ti][2] = v0 ? *(const float2*)(p0 + 8) : z2;
            fv[p][ti][3] = v1 ? *(const float2*)(p1 + 8) : z2;
        }
    };
    auto ldgw = [&](int s, int p) {
        const uint2* src = WB_pre + s * WFRAG;
#pragma unroll
        for (int q = 0; q < 5; q++) {
            int idx = tid + q * 256;
            if (idx < WFRAG) wreg[p][q] = src[idx];
        }
    };
    // plane offset in unsigned units: (buf*3 + plane)*1024 + tile*128 + lane*4
    auto stage = [&](int buf, int p) {
#pragma unroll
        for (int ti = 0; ti < 2; ti++) {
            const int toff = (s_tp * 2 + ti) * 128 + s_lane * 4;
            if (s_mat == 0) {
                unsigned hr[4];
#pragma unroll
                for (int q = 0; q < 4; q++)
                    hr[q] = packh(fv[p][ti][q].x, fv[p][ti][q].y);
                *(uint4*)(Apl + (buf * 3 + 0) * 1024 + toff) =
                    make_uint4(hr[0], hr[1], hr[2], hr[3]);
            } else {
                unsigned hr[4], lr_[4];
#pragma unroll
                for (int q = 0; q < 4; q++) {
                    float hx, lx, hy, ly;
                    splith(fv[p][ti][q].x, hx, lx);
                    splith(fv[p][ti][q].y, hy, ly);
                    hr[q]  = packh(hx, hy);
                    lr_[q] = packh(lx, ly);
                }
                *(uint4*)(Apl + (buf * 3 + 1) * 1024 + toff) =
                    make_uint4(hr[0], hr[1], hr[2], hr[3]);
                *(uint4*)(Apl + (buf * 3 + 2) * 1024 + toff) =
                    make_uint4(lr_[0], lr_[1], lr_[2], lr_[3]);
            }
        }
        uint2* wb = Wsm + buf * WFRAG;
#pragma unroll
        for (int q = 0; q < 5; q++) {
            int idx = tid + q * 256;
            if (idx < WFRAG) wb[idx] = wreg[p][q];
        }
    };

    // ---- prologue: fill pipeline 3 deep ----
    ldga(0, 0); ldgw(0, 0);
    ldga(1, 1); ldgw(1, 1);
    stage(0, 0);                 // consumes set0 (slice 0)
    ldga(2, 0); ldgw(2, 0);      // refill set0 with slice 2
    __syncthreads();

    // ---- main loop: 1 sync/slice, prefetch 3 ahead ----
    for (int s = 0; s < NSLICE; s++) {
        const int buf = s & 1;

        // A fragments: 3 planes x 2 m-tiles (conflict-free LDS.128)
        unsigned aIh[2][4], aFh[2][4], aFl[2][4];
#pragma unroll
        for (int mt = 0; mt < 2; mt++) {
            const int toff = (rgrp * 2 + mt) * 128 + lane * 4;
            uint4 h0 = *(const uint4*)(Apl + (buf * 3 + 0) * 1024 + toff);
            uint4 h1 = *(const uint4*)(Apl + (buf * 3 + 1) * 1024 + toff);
            uint4 l1 = *(const uint4*)(Apl + (buf * 3 + 2) * 1024 + toff);
            aIh[mt][0] = h0.x; aIh[mt][1] = h0.y; aIh[mt][2] = h0.z; aIh[mt][3] = h0.w;
            aFh[mt][0] = h1.x; aFh[mt][1] = h1.y; aFh[mt][2] = h1.z; aFh[mt][3] = h1.w;
            aFl[mt][0] = l1.x; aFl[mt][1] = l1.y; aFl[mt][2] = l1.z; aFl[mt][3] = l1.w;
        }

        const uint2* wb = Wsm + buf * WFRAG;
#pragma unroll
        for (int jj = 0; jj < 7; jj++) {
            if (jj < jcount) {
                const int j = jstart + jj;
                uint2 w0 = wb[(j * 3 + 0) * 32 + lane];   // WgT hi
                uint2 w1 = wb[(j * 3 + 1) * 32 + lane];   // WgB hi
                uint2 w2 = wb[(j * 3 + 2) * 32 + lane];   // Wt  hi
#pragma unroll
                for (int mt = 0; mt < 2; mt++) {
                    mma16816(accg[mt][jj], aIh[mt], w0.x, w0.y);   // gate: init @ WgT
                    mma16816(accg[mt][jj], aFh[mt], w1.x, w1.y);   // gate: fin  @ WgB
                    mma16816(acct[mt][jj], aFh[mt], w2.x, w2.y);   // transform hi
                    mma16816(acct[mt][jj], aFl[mt], w2.x, w2.y);   // transform lo
                }
            }
        }

        // stage slice s+1 into buf^1 (its set was loaded 2 iterations ago),
        // then refill that set with slice s+3.
        if (s + 1 < NSLICE) {
            const int p = (s + 1) & 1;
            stage(buf ^ 1, p);
            if (s + 3 < NSLICE) { ldga(s + 3, p); ldgw(s + 3, p); }
        }
        __syncthreads();
    }

    // ---- epilogue: sigmoid(gate)*transform -> Snw ----
#pragma unroll
    for (int mt = 0; mt < 2; mt++)
#pragma unroll
        for (int jj = 0; jj < 7; jj++) {
            if (jj < jcount) {
                const int j = jstart + jj;
                const int col = j * 8 + tig * 2;
                const int r0 = rgrp * 32 + mt * 16 + gid;
                const int r1 = r0 + 8;
                float bg0 = __ldg(&bg[col]), bg1 = __ldg(&bg[col + 1]);
                float bt0 = __ldg(&bt[col]), bt1 = __ldg(&bt[col + 1]);
                float v00 = (acct[mt][jj][0] + bt0) / (1.f + expf(-(accg[mt][jj][0] + bg0)));
                float v01 = (acct[mt][jj][1] + bt1) / (1.f + expf(-(accg[mt][jj][1] + bg1)));
                float v10 = (acct[mt][jj][2] + bt0) / (1.f + expf(-(accg[mt][jj][2] + bg0)));
                float v11 = (acct[mt][jj][3] + bt1) / (1.f + expf(-(accg[mt][jj][3] + bg1)));
                Snw[r0 * NCLS + col]     = v00;
                Snw[r0 * NCLS + col + 1] = v01;
                Snw[r1 * NCLS + col]     = v10;
                Snw[r1 * NCLS + col + 1] = v11;
            }
        }
    __syncthreads();

    // ---- sorted segmented reduction + atomic flush ----
    if (tid < NCLS) {
        float acc = 0.0f;
        int cur = -2;
        for (int r = 0; r < ROWS_B; r++) {
            int g = gid_s[r];
            if (g != cur) {
                if (cur >= 0) atomicAdd(&readout[cur * NCLS + tid], acc);
                acc = 0.0f;
                cur = g;
            }
            if (g >= 0) acc += Snw[r * NCLS + tid];
        }
        if (cur >= 0) atomicAdd(&readout[cur * NCLS + tid], acc);
    }
}

// ---------------- BN + MLP head (ILP-unrolled) ----------------
__global__ void readout_mlp(const float* __restrict__ readout,
                            const float* __restrict__ aux,
                            const float* __restrict__ gamma,
                            const float* __restrict__ beta,
                            const float* __restrict__ mean,
                            const float* __restrict__ var,
                            const float* __restrict__ W1,
                            const float* __restrict__ b1,
                            const float* __restrict__ W2,
                            const float* __restrict__ b2,
                            float* __restrict__ out)
{
    __shared__ float nrm[DIN];
    __shared__ float h[GX];
    const int g = blockIdx.x;
    const int t = threadIdx.x;   // 128 threads

    if (t < DIN) {
        float e = (t < NCLS) ? readout[g * NCLS + t] : aux[g * 2 + (t - NCLS)];
        nrm[t] = (e - mean[t]) * rsqrtf(var[t] + 1e-5f) * gamma[t] + beta[t];
    }
    __syncthreads();

    {
        float s0 = b1[t], s1 = 0.f, s2 = 0.f, s3 = 0.f;
#pragma unroll
        for (int k = 0; k < 104; k += 4) {
            s0 += nrm[k]     * W1[(k)     * GX + t];
            s1 += nrm[k + 1] * W1[(k + 1) * GX + t];
            s2 += nrm[k + 2] * W1[(k + 2) * GX + t];
            s3 += nrm[k + 3] * W1[(k + 3) * GX + t];
        }
        s0 += nrm[104] * W1[104 * GX + t];
        s1 += nrm[105] * W1[105 * GX + t];
        h[t] = fmaxf((s0 + s1) + (s2 + s3), 0.0f);
    }
    __syncthreads();

    if (t < NCLS) {
        float s0 = b2[t], s1 = 0.f, s2 = 0.f, s3 = 0.f;
#pragma unroll
        for (int k = 0; k < GX; k += 4) {
            s0 += h[k]     * W2[(k)     * NCLS + t];
            s1 += h[k + 1] * W2[(k + 1) * NCLS + t];
            s2 += h[k + 2] * W2[(k + 2) * NCLS + t];
            s3 += h[k + 3] * W2[(k + 3) * NCLS + t];
        }
        out[g * NCLS + t] = (s0 + s1) + (s2 + s3);
    }
}

// ---------------- launch ----------------
extern "C" void kernel_launch(void* const* d_in, const int* in_sizes, int n_in,
                              void* d_out, int out_size)
{
    const float* init_ns = (const float*)d_in[0];
    const float* fin_ns  = (const float*)d_in[1];
    const float* aux     = (const float*)d_in[2];
    const int*   gids    = (const int*)d_in[3];
    const float* Wg  = (const float*)d_in[5];
    const float* bg  = (const float*)d_in[6];
    const float* Wt  = (const float*)d_in[7];
    const float* bt  = (const float*)d_in[8];
    const float* gma = (const float*)d_in[9];
    const float* bta = (const float*)d_in[10];
    const float* mn  = (const float*)d_in[11];
    const float* vr  = (const float*)d_in[12];
    const float* W1  = (const float*)d_in[13];
    const float* b1  = (const float*)d_in[14];
    const float* W2  = (const float*)d_in[15];
    const float* b2  = (const float*)d_in[16];
    float* out = (float*)d_out;

    const int N = in_sizes[0] / HIDDEN;
    int G = in_sizes[2] / 2;
    if (G > MAXG) G = MAXG;

    float* readout_ptr = nullptr;
    cudaGetSymbolAddress((void**)&readout_ptr, g_readout);

    const int smem_bytes = 53760;
    cudaFuncSetAttribute(readout_mma, cudaFuncAttributeMaxDynamicSharedMemorySize,
                         smem_bytes);

    zero_readout_k<<<(G * NCLS + 255) / 256, 256>>>(readout_ptr, G * NCLS);

    const int wtotal = NSLICE * WFRAG;
    prep_weights<<<(wtotal + 255) / 256, 256>>>(Wg, Wt);

    const int blocks = (N + ROWS_B - 1) / ROWS_B;
    readout_mma<<<blocks, 256, smem_bytes>>>(init_ns, fin_ns, gids,
                                             bg, bt, readout_ptr, N);

    readout_mlp<<<G, GX>>>(readout_ptr, aux, gma, bta, mn, vr, W1, b1, W2, b2, out);
}

// round 12
// speedup vs baseline: 1.4591x; 1.4591x over previous
#include <cuda_runtime.h>
#include <cuda_fp16.h>
#include <cstdint>
#include <math.h>

#define HIDDEN   256
#define NCLS     104
#define DIN      106
#define GX       128
#define NT       13          // n-tiles of 8
#define NSLICE   16          // k-slices of 16 (K=256)
#define ROWS_B   128         // rows per block
#define MAXG     4096
#define WFRAG    (NT * 3 * 32)   // 1248 uint2 fragments per k-slice

// ---------------- device scratch (no cudaMalloc allowed) ----------------
__device__ float g_readout[MAXG * NCLS];
// Pre-packed fp16 weight B-fragments: [slice][ntile][stream][lane] -> {b0,b1}
// stream 0 = Wg rows [0,256), 1 = Wg rows [256,512), 2 = Wt
__device__ uint2 WB_pre[NSLICE * WFRAG];

// ---------------- helpers ----------------
__device__ __forceinline__ unsigned packh(float a, float b) {
    __half2 t = __floats2half2_rn(a, b);
    return *reinterpret_cast<unsigned*>(&t);
}
__device__ __forceinline__ void mma16816(float c[4], const unsigned a[4],
                                         unsigned b0, unsigned b1) {
    asm volatile(
        "mma.sync.aligned.m16n8k16.row.col.f32.f16.f16.f32 "
        "{%0,%1,%2,%3}, {%4,%5,%6,%7}, {%8,%9}, {%0,%1,%2,%3};"
        : "+f"(c[0]), "+f"(c[1]), "+f"(c[2]), "+f"(c[3])
        : "r"(a[0]), "r"(a[1]), "r"(a[2]), "r"(a[3]), "r"(b0), "r"(b1));
}

// ---------------- prep kernels ----------------
__global__ void zero_readout_k(float* __restrict__ p, int n) {
    int i = blockIdx.x * blockDim.x + threadIdx.x;
    if (i < n) p[i] = 0.0f;
}

__global__ void prep_weights(const float* __restrict__ Wg,
                             const float* __restrict__ Wt) {
    int idx = blockIdx.x * blockDim.x + threadIdx.x;
    if (idx >= NSLICE * WFRAG) return;
    int lane = idx & 31;
    int rest = idx >> 5;
    int stream = rest % 3; rest /= 3;
    int j = rest % NT;
    int s = rest / NT;
    int n = j * 8 + (lane >> 2);
    int kk = (lane & 3) * 2;
    int k0 = s * 16;

    float v[4];
    const int koffs[4] = {kk, kk + 1, kk + 8, kk + 9};
#pragma unroll
    for (int q = 0; q < 4; q++) {
        int k = k0 + koffs[q];
        float val;
        if (stream == 0)      val = Wg[k * NCLS + n];
        else if (stream == 1) val = Wg[(256 + k) * NCLS + n];
        else                  val = Wt[k * NCLS + n];
        v[q] = val;
    }
    WB_pre[idx] = make_uint2(packh(v[0], v[1]), packh(v[2], v[3]));
}

// ---------------- main fused kernel ----------------
// smem layout (dynamic, 53760 B):
//   [0      , 16384)  A planes: unsigned[2 buf][2 plane][8 tile][32 lane][4]
//                     plane 0 = init_hi, 1 = fin_hi   (16B lane stride, conflict-free)
//   [16384  , 36352)  Wsm: uint2[2 buf][1248]
//   [0      , 53248)  Snw: float[128][104]   (epilogue reuse)
//   [53248  , 53760)  gid_s: int[128]
extern "C" __global__ void __launch_bounds__(256, 1)
readout_mma(const float* __restrict__ init_ns,
            const float* __restrict__ fin_ns,
            const int*   __restrict__ gids,
            const float* __restrict__ bg,
            const float* __restrict__ bt,
            float*       __restrict__ readout,
            int N)
{
    extern __shared__ char smraw[];
    unsigned* Apl   = (unsigned*)smraw;                 // plane base, unsigned units
    uint2*    Wsm   = (uint2*)(smraw + 16384);
    float*    Snw   = (float*)smraw;
    int*      gid_s = (int*)(smraw + 53248);

    const int tid = threadIdx.x;
    const int n0  = blockIdx.x * ROWS_B;
    const int nvalid = min(ROWS_B, N - n0);

    if (tid < ROWS_B) gid_s[tid] = (tid < nvalid) ? gids[n0 + tid] : -1;

    // ---- compute-side identities ----
    const int w     = tid >> 5;
    const int lane  = tid & 31;
    const int wset  = w >> 2;            // 0: ntiles 0-6, 1: ntiles 7-12
    const int rgrp  = w & 3;             // which 32-row group
    const int jstart = wset * 7;
    const int jcount = wset ? 6 : 7;
    const int gid   = lane >> 2;
    const int tig   = lane & 3;

    float accg[2][7][4];
    float acct[2][7][4];
#pragma unroll
    for (int mt = 0; mt < 2; mt++)
#pragma unroll
        for (int jj = 0; jj < 7; jj++)
#pragma unroll
            for (int q = 0; q < 4; q++) { accg[mt][jj][q] = 0.f; acct[mt][jj][q] = 0.f; }

    // ---- staging identities: thread -> (mat/plane, tilepair, lane) ----
    const int s_mat  = tid >> 7;          // 0 init, 1 fin  (== A plane)
    const int s_tp   = (tid >> 5) & 3;    // tile pair
    const int s_lane = tid & 31;
    const int s_gid  = s_lane >> 2;
    const int s_tig  = s_lane & 3;
    const float* s_base = s_mat ? fin_ns : init_ns;

    float2 fv[2][4];
    uint2  wreg[5];

    const float2 z2 = make_float2(0.f, 0.f);

    auto ldga = [&](int s) {
#pragma unroll
        for (int ti = 0; ti < 2; ti++) {
            int tile = s_tp * 2 + ti;
            int r0 = tile * 16 + s_gid;
            int r1 = r0 + 8;
            const float* p0 = s_base + (size_t)(n0 + r0) * HIDDEN + s * 16 + s_tig * 2;
            const float* p1 = s_base + (size_t)(n0 + r1) * HIDDEN + s * 16 + s_tig * 2;
            bool v0 = r0 < nvalid, v1 = r1 < nvalid;
            fv[ti][0] = v0 ? *(const float2*)p0       : z2;
            fv[ti][1] = v1 ? *(const float2*)p1       : z2;
            fv[ti][2] = v0 ? *(const float2*)(p0 + 8) : z2;
            fv[ti][3] = v1 ? *(const float2*)(p1 + 8) : z2;
        }
    };
    auto ldgw = [&](int s) {
        const uint2* src = WB_pre + s * WFRAG;
#pragma unroll
        for (int q = 0; q < 5; q++) {
            int idx = tid + q * 256;
            if (idx < WFRAG) wreg[q] = src[idx];
        }
    };
    // plane offset in unsigned units: (buf*2 + plane)*1024 + tile*128 + lane*4
    auto stage = [&](int buf) {
#pragma unroll
        for (int ti = 0; ti < 2; ti++) {
            const int toff = (s_tp * 2 + ti) * 128 + s_lane * 4;
            unsigned hr[4];
#pragma unroll
            for (int q = 0; q < 4; q++)
                hr[q] = packh(fv[ti][q].x, fv[ti][q].y);
            *(uint4*)(Apl + (buf * 2 + s_mat) * 1024 + toff) =
                make_uint4(hr[0], hr[1], hr[2], hr[3]);
        }
        uint2* wb = Wsm + buf * WFRAG;
#pragma unroll
        for (int q = 0; q < 5; q++) {
            int idx = tid + q * 256;
            if (idx < WFRAG) wb[idx] = wreg[q];
        }
    };

    // ---- main pipeline (R9 schedule: LDG covered by full compute phase) ----
    ldga(0); ldgw(0);
    for (int s = 0; s < NSLICE; s++) {
        const int buf = s & 1;
        stage(buf);
        __syncthreads();
        if (s + 1 < NSLICE) { ldga(s + 1); ldgw(s + 1); }

        // A fragments: 2 planes x 2 m-tiles (conflict-free LDS.128)
        unsigned aIh[2][4], aFh[2][4];
#pragma unroll
        for (int mt = 0; mt < 2; mt++) {
            const int toff = (rgrp * 2 + mt) * 128 + lane * 4;
            uint4 h0 = *(const uint4*)(Apl + (buf * 2 + 0) * 1024 + toff);
            uint4 h1 = *(const uint4*)(Apl + (buf * 2 + 1) * 1024 + toff);
            aIh[mt][0] = h0.x; aIh[mt][1] = h0.y; aIh[mt][2] = h0.z; aIh[mt][3] = h0.w;
            aFh[mt][0] = h1.x; aFh[mt][1] = h1.y; aFh[mt][2] = h1.z; aFh[mt][3] = h1.w;
        }

        const uint2* wb = Wsm + buf * WFRAG;
#pragma unroll
        for (int jj = 0; jj < 7; jj++) {
            if (jj < jcount) {
                const int j = jstart + jj;
                uint2 w0 = wb[(j * 3 + 0) * 32 + lane];   // WgT
                uint2 w1 = wb[(j * 3 + 1) * 32 + lane];   // WgB
                uint2 w2 = wb[(j * 3 + 2) * 32 + lane];   // Wt
#pragma unroll
                for (int mt = 0; mt < 2; mt++) {
                    mma16816(accg[mt][jj], aIh[mt], w0.x, w0.y);   // gate: init @ WgT
                    mma16816(accg[mt][jj], aFh[mt], w1.x, w1.y);   // gate: fin  @ WgB
                    mma16816(acct[mt][jj], aFh[mt], w2.x, w2.y);   // transform
                }
            }
        }
        __syncthreads();
    }

    // ---- epilogue: sigmoid(gate)*transform -> Snw ----
#pragma unroll
    for (int mt = 0; mt < 2; mt++)
#pragma unroll
        for (int jj = 0; jj < 7; jj++) {
            if (jj < jcount) {
                const int j = jstart + jj;
                const int col = j * 8 + tig * 2;
                const int r0 = rgrp * 32 + mt * 16 + gid;
                const int r1 = r0 + 8;
                float bg0 = __ldg(&bg[col]), bg1 = __ldg(&bg[col + 1]);
                float bt0 = __ldg(&bt[col]), bt1 = __ldg(&bt[col + 1]);
                float v00 = (acct[mt][jj][0] + bt0) / (1.f + __expf(-(accg[mt][jj][0] + bg0)));
                float v01 = (acct[mt][jj][1] + bt1) / (1.f + __expf(-(accg[mt][jj][1] + bg1)));
                float v10 = (acct[mt][jj][2] + bt0) / (1.f + __expf(-(accg[mt][jj][2] + bg0)));
                float v11 = (acct[mt][jj][3] + bt1) / (1.f + __expf(-(accg[mt][jj][3] + bg1)));
                Snw[r0 * NCLS + col]     = v00;
                Snw[r0 * NCLS + col + 1] = v01;
                Snw[r1 * NCLS + col]     = v10;
                Snw[r1 * NCLS + col + 1] = v11;
            }
        }
    __syncthreads();

    // ---- sorted segmented reduction + atomic flush ----
    if (tid < NCLS) {
        float acc = 0.0f;
        int cur = -2;
        for (int r = 0; r < ROWS_B; r++) {
            int g = gid_s[r];
            if (g != cur) {
                if (cur >= 0) atomicAdd(&readout[cur * NCLS + tid], acc);
                acc = 0.0f;
                cur = g;
            }
            if (g >= 0) acc += Snw[r * NCLS + tid];
        }
        if (cur >= 0) atomicAdd(&readout[cur * NCLS + tid], acc);
    }
}

// ---------------- BN + MLP head (ILP-unrolled) ----------------
__global__ void readout_mlp(const float* __restrict__ readout,
                            const float* __restrict__ aux,
                            const float* __restrict__ gamma,
                            const float* __restrict__ beta,
                            const float* __restrict__ mean,
                            const float* __restrict__ var,
                            const float* __restrict__ W1,
                            const float* __restrict__ b1,
                            const float* __restrict__ W2,
                            const float* __restrict__ b2,
                            float* __restrict__ out)
{
    __shared__ float nrm[DIN];
    __shared__ float h[GX];
    const int g = blockIdx.x;
    const int t = threadIdx.x;   // 128 threads

    if (t < DIN) {
        float e = (t < NCLS) ? readout[g * NCLS + t] : aux[g * 2 + (t - NCLS)];
        nrm[t] = (e - mean[t]) * rsqrtf(var[t] + 1e-5f) * gamma[t] + beta[t];
    }
    __syncthreads();

    {
        float s0 = b1[t], s1 = 0.f, s2 = 0.f, s3 = 0.f;
#pragma unroll
        for (int k = 0; k < 104; k += 4) {
            s0 += nrm[k]     * W1[(k)     * GX + t];
            s1 += nrm[k + 1] * W1[(k + 1) * GX + t];
            s2 += nrm[k + 2] * W1[(k + 2) * GX + t];
            s3 += nrm[k + 3] * W1[(k + 3) * GX + t];
        }
        s0 += nrm[104] * W1[104 * GX + t];
        s1 += nrm[105] * W1[105 * GX + t];
        h[t] = fmaxf((s0 + s1) + (s2 + s3), 0.0f);
    }
    __syncthreads();

    if (t < NCLS) {
        float s0 = b2[t], s1 = 0.f, s2 = 0.f, s3 = 0.f;
#pragma unroll
        for (int k = 0; k < GX; k += 4) {
            s0 += h[k]     * W2[(k)     * NCLS + t];
            s1 += h[k + 1] * W2[(k + 1) * NCLS + t];
            s2 += h[k + 2] * W2[(k + 2) * NCLS + t];
            s3 += h[k + 3] * W2[(k + 3) * NCLS + t];
        }
        out[g * NCLS + t] = (s0 + s1) + (s2 + s3);
    }
}

// ---------------- launch ----------------
extern "C" void kernel_launch(void* const* d_in, const int* in_sizes, int n_in,
                              void* d_out, int out_size)
{
    const float* init_ns = (const float*)d_in[0];
    const float* fin_ns  = (const float*)d_in[1];
    const float* aux     = (const float*)d_in[2];
    const int*   gids    = (const int*)d_in[3];
    const float* Wg  = (const float*)d_in[5];
    const float* bg  = (const float*)d_in[6];
    const float* Wt  = (const float*)d_in[7];
    const float* bt  = (const float*)d_in[8];
    const float* gma = (const float*)d_in[9];
    const float* bta = (const float*)d_in[10];
    const float* mn  = (const float*)d_in[11];
    const float* vr  = (const float*)d_in[12];
    const float* W1  = (const float*)d_in[13];
    const float* b1  = (const float*)d_in[14];
    const float* W2  = (const float*)d_in[15];
    const float* b2  = (const float*)d_in[16];
    float* out = (float*)d_out;

    const int N = in_sizes[0] / HIDDEN;
    int G = in_sizes[2] / 2;
    if (G > MAXG) G = MAXG;

    float* readout_ptr = nullptr;
    cudaGetSymbolAddress((void**)&readout_ptr, g_readout);

    const int smem_bytes = 53760;
    cudaFuncSetAttribute(readout_mma, cudaFuncAttributeMaxDynamicSharedMemorySize,
                         smem_bytes);

    zero_readout_k<<<(G * NCLS + 255) / 256, 256>>>(readout_ptr, G * NCLS);

    const int wtotal = NSLICE * WFRAG;
    prep_weights<<<(wtotal + 255) / 256, 256>>>(Wg, Wt);

    const int blocks = (N + ROWS_B - 1) / ROWS_B;
    readout_mma<<<blocks, 256, smem_bytes>>>(init_ns, fin_ns, gids,
                                             bg, bt, readout_ptr, N);

    readout_mlp<<<G, GX>>>(readout_ptr, aux, gma, bta, mn, vr, W1, b1, W2, b2, out);
}

// round 14
// speedup vs baseline: 1.7069x; 1.1698x over previous
#include <cuda_runtime.h>
#include <cuda_fp16.h>
#include <cstdint>
#include <math.h>

#define HIDDEN   256
#define NCLS     104
#define DIN      106
#define GX       128
#define NT       13          // n-tiles of 8
#define NSLICE   16          // k-slices of 16 (K=256)
#define ROWS_B   64          // rows per block (4 m-tiles)
#define MAXG     4096
#define WFRAG    (NT * 3 * 32)   // 1248 uint2 fragments per k-slice

// ---------------- device scratch (no cudaMalloc allowed) ----------------
__device__ float g_readout[MAXG * NCLS];
// Pre-packed fp16 weight B-fragments: [slice][ntile][stream][lane] -> {b0,b1}
// stream 0 = Wg rows [0,256), 1 = Wg rows [256,512), 2 = Wt
__device__ uint2 WB_pre[NSLICE * WFRAG];

// ---------------- helpers ----------------
__device__ __forceinline__ unsigned packh(float a, float b) {
    __half2 t = __floats2half2_rn(a, b);
    return *reinterpret_cast<unsigned*>(&t);
}
__device__ __forceinline__ void mma16816(float c[4], const unsigned a[4],
                                         unsigned b0, unsigned b1) {
    asm volatile(
        "mma.sync.aligned.m16n8k16.row.col.f32.f16.f16.f32 "
        "{%0,%1,%2,%3}, {%4,%5,%6,%7}, {%8,%9}, {%0,%1,%2,%3};"
        : "+f"(c[0]), "+f"(c[1]), "+f"(c[2]), "+f"(c[3])
        : "r"(a[0]), "r"(a[1]), "r"(a[2]), "r"(a[3]), "r"(b0), "r"(b1));
}

// ---------------- prep kernels ----------------
__global__ void zero_readout_k(float* __restrict__ p, int n) {
    int i = blockIdx.x * blockDim.x + threadIdx.x;
    if (i < n) p[i] = 0.0f;
}

__global__ void prep_weights(const float* __restrict__ Wg,
                             const float* __restrict__ Wt) {
    int idx = blockIdx.x * blockDim.x + threadIdx.x;
    if (idx >= NSLICE * WFRAG) return;
    int lane = idx & 31;
    int rest = idx >> 5;
    int stream = rest % 3; rest /= 3;
    int j = rest % NT;
    int s = rest / NT;
    int n = j * 8 + (lane >> 2);
    int kk = (lane & 3) * 2;
    int k0 = s * 16;

    float v[4];
    const int koffs[4] = {kk, kk + 1, kk + 8, kk + 9};
#pragma unroll
    for (int q = 0; q < 4; q++) {
        int k = k0 + koffs[q];
        float val;
        if (stream == 0)      val = Wg[k * NCLS + n];
        else if (stream == 1) val = Wg[(256 + k) * NCLS + n];
        else                  val = Wt[k * NCLS + n];
        v[q] = val;
    }
    WB_pre[idx] = make_uint2(packh(v[0], v[1]), packh(v[2], v[3]));
}

// ---------------- main fused kernel ----------------
// smem layout (dynamic, 28416 B):
//   [0      , 8192 )  A planes: unsigned[2 buf][2 mat][4 tile][32 lane][4]
//                     mat 0 = init, 1 = fin   (16B lane stride, conflict-free)
//   [8192   , 28160)  Wsm: uint2[2 buf][1248]
//   [0      , 26624)  Snw: float[64][104]   (epilogue reuse)
//   [28160  , 28416)  gid_s: int[64]
extern "C" __global__ void __launch_bounds__(256, 2)
readout_mma(const float* __restrict__ init_ns,
            const float* __restrict__ fin_ns,
            const int*   __restrict__ gids,
            const float* __restrict__ bg,
            const float* __restrict__ bt,
            float*       __restrict__ readout,
            int N)
{
    extern __shared__ char smraw[];
    unsigned* Apl   = (unsigned*)smraw;                 // plane base, unsigned units
    uint2*    Wsm   = (uint2*)(smraw + 8192);
    float*    Snw   = (float*)smraw;
    int*      gid_s = (int*)(smraw + 28160);

    const int tid = threadIdx.x;
    const int n0  = blockIdx.x * ROWS_B;
    const int nvalid = min(ROWS_B, N - n0);

    if (tid < ROWS_B) gid_s[tid] = (tid < nvalid) ? gids[n0 + tid] : -1;

    // ---- compute-side identities: warp -> (m-tile, ntile half) ----
    const int w     = tid >> 5;
    const int lane  = tid & 31;
    const int mt    = w & 3;             // m-tile 0..3 (16 rows each)
    const int wset  = w >> 2;            // 0: ntiles 0-6, 1: ntiles 7-12
    const int jstart = wset * 7;
    const int jcount = wset ? 6 : 7;
    const int gid   = lane >> 2;
    const int tig   = lane & 3;

    float accg[7][4];
    float acct[7][4];
#pragma unroll
    for (int jj = 0; jj < 7; jj++)
#pragma unroll
        for (int q = 0; q < 4; q++) { accg[jj][q] = 0.f; acct[jj][q] = 0.f; }

    // ---- staging identities: thread -> (mat, tile, lane) ----
    const int s_mat  = tid >> 7;          // 0 init, 1 fin
    const int s_tile = (tid >> 5) & 3;    // m-tile
    const int s_lane = tid & 31;
    const int s_gid  = s_lane >> 2;
    const int s_tig  = s_lane & 3;
    const float* s_base = s_mat ? fin_ns : init_ns;

    float2 fv[4];
    uint2  wreg[5];

    const float2 z2 = make_float2(0.f, 0.f);

    auto ldga = [&](int s) {
        int r0 = s_tile * 16 + s_gid;
        int r1 = r0 + 8;
        const float* p0 = s_base + (size_t)(n0 + r0) * HIDDEN + s * 16 + s_tig * 2;
        const float* p1 = s_base + (size_t)(n0 + r1) * HIDDEN + s * 16 + s_tig * 2;
        bool v0 = r0 < nvalid, v1 = r1 < nvalid;
        fv[0] = v0 ? *(const float2*)p0       : z2;
        fv[1] = v1 ? *(const float2*)p1       : z2;
        fv[2] = v0 ? *(const float2*)(p0 + 8) : z2;
        fv[3] = v1 ? *(const float2*)(p1 + 8) : z2;
    };
    auto ldgw = [&](int s) {
        const uint2* src = WB_pre + s * WFRAG;
#pragma unroll
        for (int q = 0; q < 5; q++) {
            int idx = tid + q * 256;
            if (idx < WFRAG) wreg[q] = src[idx];
        }
    };
    // plane offset in unsigned units: (buf*2 + mat)*512 + tile*128 + lane*4
    auto stage = [&](int buf) {
        unsigned hr[4];
#pragma unroll
        for (int q = 0; q < 4; q++)
            hr[q] = packh(fv[q].x, fv[q].y);
        *(uint4*)(Apl + (buf * 2 + s_mat) * 512 + s_tile * 128 + s_lane * 4) =
            make_uint4(hr[0], hr[1], hr[2], hr[3]);
        uint2* wb = Wsm + buf * WFRAG;
#pragma unroll
        for (int q = 0; q < 5; q++) {
            int idx = tid + q * 256;
            if (idx < WFRAG) wb[idx] = wreg[q];
        }
    };

    // ---- main pipeline: ONE sync per slice (double buffer covers the rest) ----
    ldga(0); ldgw(0);
    for (int s = 0; s < NSLICE; s++) {
        const int buf = s & 1;
        stage(buf);
        __syncthreads();
        if (s + 1 < NSLICE) { ldga(s + 1); ldgw(s + 1); }

        // A fragments: 2 mats x 1 m-tile (conflict-free LDS.128)
        unsigned aIh[4], aFh[4];
        {
            const int toff = mt * 128 + lane * 4;
            uint4 h0 = *(const uint4*)(Apl + (buf * 2 + 0) * 512 + toff);
            uint4 h1 = *(const uint4*)(Apl + (buf * 2 + 1) * 512 + toff);
            aIh[0] = h0.x; aIh[1] = h0.y; aIh[2] = h0.z; aIh[3] = h0.w;
            aFh[0] = h1.x; aFh[1] = h1.y; aFh[2] = h1.z; aFh[3] = h1.w;
        }

        const uint2* wb = Wsm + buf * WFRAG;
#pragma unroll
        for (int jj = 0; jj < 7; jj++) {
            if (jj < jcount) {
                const int j = jstart + jj;
                uint2 w0 = wb[(j * 3 + 0) * 32 + lane];   // WgT
                uint2 w1 = wb[(j * 3 + 1) * 32 + lane];   // WgB
                uint2 w2 = wb[(j * 3 + 2) * 32 + lane];   // Wt
                mma16816(accg[jj], aIh, w0.x, w0.y);   // gate: init @ WgT
                mma16816(accg[jj], aFh, w1.x, w1.y);   // gate: fin  @ WgB
                mma16816(acct[jj], aFh, w2.x, w2.y);   // transform
            }
        }
        // no trailing sync: next iter's stage writes buf^1; the next write to
        // THIS buf is at iter s+2, after barrier(s+1) which follows all
        // compute-of-s reads in every thread's program order. Race-free.
    }
    __syncthreads();   // protect Snw (aliases A/W smem) from last compute reads

    // ---- epilogue: sigmoid(gate)*transform -> Snw ----
#pragma unroll
    for (int jj = 0; jj < 7; jj++) {
        if (jj < jcount) {
            const int j = jstart + jj;
            const int col = j * 8 + tig * 2;
            const int r0 = mt * 16 + gid;
            const int r1 = r0 + 8;
            float bg0 = __ldg(&bg[col]), bg1 = __ldg(&bg[col + 1]);
            float bt0 = __ldg(&bt[col]), bt1 = __ldg(&bt[col + 1]);
            float v00 = (acct[jj][0] + bt0) / (1.f + __expf(-(accg[jj][0] + bg0)));
            float v01 = (acct[jj][1] + bt1) / (1.f + __expf(-(accg[jj][1] + bg1)));
            float v10 = (acct[jj][2] + bt0) / (1.f + __expf(-(accg[jj][2] + bg0)));
            float v11 = (acct[jj][3] + bt1) / (1.f + __expf(-(accg[jj][3] + bg1)));
            Snw[r0 * NCLS + col]     = v00;
            Snw[r0 * NCLS + col + 1] = v01;
            Snw[r1 * NCLS + col]     = v10;
            Snw[r1 * NCLS + col + 1] = v11;
        }
    }
    __syncthreads();

    // ---- sorted segmented reduction + atomic flush ----
    if (tid < NCLS) {
        float acc = 0.0f;
        int cur = -2;
        for (int r = 0; r < ROWS_B; r++) {
            int g = gid_s[r];
            if (g != cur) {
                if (cur >= 0) atomicAdd(&readout[cur * NCLS + tid], acc);
                acc = 0.0f;
                cur = g;
            }
            if (g >= 0) acc += Snw[r * NCLS + tid];
        }
        if (cur >= 0) atomicAdd(&readout[cur * NCLS + tid], acc);
    }
}

// ---------------- BN + MLP head (ILP-unrolled) ----------------
__global__ void readout_mlp(const float* __restrict__ readout,
                            const float* __restrict__ aux,
                            const float* __restrict__ gamma,
                            const float* __restrict__ beta,
                            const float* __restrict__ mean,
                            const float* __restrict__ var,
                            const float* __restrict__ W1,
                            const float* __restrict__ b1,
                            const float* __restrict__ W2,
                            const float* __restrict__ b2,
                            float* __restrict__ out)
{
    __shared__ float nrm[DIN];
    __shared__ float h[GX];
    const int g = blockIdx.x;
    const int t = threadIdx.x;   // 128 threads

    if (t < DIN) {
        float e = (t < NCLS) ? readout[g * NCLS + t] : aux[g * 2 + (t - NCLS)];
        nrm[t] = (e - mean[t]) * rsqrtf(var[t] + 1e-5f) * gamma[t] + beta[t];
    }
    __syncthreads();

    {
        float s0 = b1[t], s1 = 0.f, s2 = 0.f, s3 = 0.f;
#pragma unroll
        for (int k = 0; k < 104; k += 4) {
            s0 += nrm[k]     * W1[(k)     * GX + t];
            s1 += nrm[k + 1] * W1[(k + 1) * GX + t];
            s2 += nrm[k + 2] * W1[(k + 2) * GX + t];
            s3 += nrm[k + 3] * W1[(k + 3) * GX + t];
        }
        s0 += nrm[104] * W1[104 * GX + t];
        s1 += nrm[105] * W1[105 * GX + t];
        h[t] = fmaxf((s0 + s1) + (s2 + s3), 0.0f);
    }
    __syncthreads();

    if (t < NCLS) {
        float s0 = b2[t], s1 = 0.f, s2 = 0.f, s3 = 0.f;
#pragma unroll
        for (int k = 0; k < GX; k += 4) {
            s0 += h[k]     * W2[(k)     * NCLS + t];
            s1 += h[k + 1] * W2[(k + 1) * NCLS + t];
            s2 += h[k + 2] * W2[(k + 2) * NCLS + t];
            s3 += h[k + 3] * W2[(k + 3) * NCLS + t];
        }
        out[g * NCLS + t] = (s0 + s1) + (s2 + s3);
    }
}

// ---------------- launch ----------------
extern "C" void kernel_launch(void* const* d_in, const int* in_sizes, int n_in,
                              void* d_out, int out_size)
{
    const float* init_ns = (const float*)d_in[0];
    const float* fin_ns  = (const float*)d_in[1];
    const float* aux     = (const float*)d_in[2];
    const int*   gids    = (const int*)d_in[3];
    const float* Wg  = (const float*)d_in[5];
    const float* bg  = (const float*)d_in[6];
    const float* Wt  = (const float*)d_in[7];
    const float* bt  = (const float*)d_in[8];
    const float* gma = (const float*)d_in[9];
    const float* bta = (const float*)d_in[10];
    const float* mn  = (const float*)d_in[11];
    const float* vr  = (const float*)d_in[12];
    const float* W1  = (const float*)d_in[13];
    const float* b1  = (const float*)d_in[14];
    const float* W2  = (const float*)d_in[15];
    const float* b2  = (const float*)d_in[16];
    float* out = (float*)d_out;

    const int N = in_sizes[0] / HIDDEN;
    int G = in_sizes[2] / 2;
    if (G > MAXG) G = MAXG;

    float* readout_ptr = nullptr;
    cudaGetSymbolAddress((void**)&readout_ptr, g_readout);

    const int smem_bytes = 28416;
    cudaFuncSetAttribute(readout_mma, cudaFuncAttributeMaxDynamicSharedMemorySize,
                         smem_bytes);

    zero_readout_k<<<(G * NCLS + 255) / 256, 256>>>(readout_ptr, G * NCLS);

    const int wtotal = NSLICE * WFRAG;
    prep_weights<<<(wtotal + 255) / 256, 256>>>(Wg, Wt);

    const int blocks = (N + ROWS_B - 1) / ROWS_B;
    readout_mma<<<blocks, 256, smem_bytes>>>(init_ns, fin_ns, gids,
                                             bg, bt, readout_ptr, N);

    readout_mlp<<<G, GX>>>(readout_ptr, aux, gma, bta, mn, vr, W1, b1, W2, b2, out);
}